// round 4
// baseline (speedup 1.0000x reference)
#include <cuda_runtime.h>

// out[t, :] = W[seq[t], :] + W[pre[t], :] + W[post[t], :]
// D = 128 floats (512B row). One warp per 8 tokens; lane l handles float4 #l.
// All 24 row gathers issued back-to-back (max MLP) before any consume.
// Weights via __ldcg (no L1 reuse for random gathers), output via __stcs
// (don't evict the 51MB table from L2).

#define EMBED_VEC 32
#define THREADS_PER_BLOCK 256
#define WARPS_PER_BLOCK (THREADS_PER_BLOCK / 32)
#define TPW 8   // tokens per warp

__global__ __launch_bounds__(THREADS_PER_BLOCK, 2)
void cbow_subword_kernel(const int* __restrict__ seq,
                         const int* __restrict__ pre,
                         const int* __restrict__ post,
                         const float4* __restrict__ W,
                         float4* __restrict__ out,
                         int n_tok) {
    int warp = blockIdx.x * WARPS_PER_BLOCK + (threadIdx.x >> 5);
    int lane = threadIdx.x & 31;
    long long t0 = (long long)warp * TPW;
    if (t0 >= n_tok) return;

    if (t0 + TPW <= n_tok) {
        // Vectorized index loads: 2x int4 per array (t0 is 8-aligned).
        int4 s0 = __ldg((const int4*)(seq  + t0));
        int4 s1 = __ldg((const int4*)(seq  + t0) + 1);
        int4 p0 = __ldg((const int4*)(pre  + t0));
        int4 p1 = __ldg((const int4*)(pre  + t0) + 1);
        int4 q0 = __ldg((const int4*)(post + t0));
        int4 q1 = __ldg((const int4*)(post + t0) + 1);
        int ia[TPW] = {s0.x, s0.y, s0.z, s0.w, s1.x, s1.y, s1.z, s1.w};
        int ib[TPW] = {p0.x, p0.y, p0.z, p0.w, p1.x, p1.y, p1.z, p1.w};
        int ic[TPW] = {q0.x, q0.y, q0.z, q0.w, q1.x, q1.y, q1.z, q1.w};

        // 24 independent gathers, all issued before first use.
        float4 va[TPW], vb[TPW], vc[TPW];
        #pragma unroll
        for (int j = 0; j < TPW; j++) va[j] = __ldcg(W + (size_t)ia[j] * EMBED_VEC + lane);
        #pragma unroll
        for (int j = 0; j < TPW; j++) vb[j] = __ldcg(W + (size_t)ib[j] * EMBED_VEC + lane);
        #pragma unroll
        for (int j = 0; j < TPW; j++) vc[j] = __ldcg(W + (size_t)ic[j] * EMBED_VEC + lane);

        #pragma unroll
        for (int j = 0; j < TPW; j++) {
            float4 r;
            r.x = va[j].x + vb[j].x + vc[j].x;
            r.y = va[j].y + vb[j].y + vc[j].y;
            r.z = va[j].z + vb[j].z + vc[j].z;
            r.w = va[j].w + vb[j].w + vc[j].w;
            __stcs(out + (size_t)(t0 + j) * EMBED_VEC + lane, r);
        }
    } else {
        // Tail (n_tok % 8 != 0 case; not hit for 131072).
        for (long long t = t0; t < n_tok; t++) {
            int i0 = __ldg(seq + t), i1 = __ldg(pre + t), i2 = __ldg(post + t);
            float4 a = __ldcg(W + (size_t)i0 * EMBED_VEC + lane);
            float4 b = __ldcg(W + (size_t)i1 * EMBED_VEC + lane);
            float4 c = __ldcg(W + (size_t)i2 * EMBED_VEC + lane);
            float4 r;
            r.x = a.x + b.x + c.x;
            r.y = a.y + b.y + c.y;
            r.z = a.z + b.z + c.z;
            r.w = a.w + b.w + c.w;
            __stcs(out + (size_t)t * EMBED_VEC + lane, r);
        }
    }
}

extern "C" void kernel_launch(void* const* d_in, const int* in_sizes, int n_in,
                              void* d_out, int out_size) {
    const int*    seq  = (const int*)d_in[0];
    const int*    pre  = (const int*)d_in[1];
    const int*    post = (const int*)d_in[2];
    const float4* W    = (const float4*)d_in[3];
    float4*       out  = (float4*)d_out;

    int n_tok = in_sizes[0];  // 131072
    int tokens_per_block = WARPS_PER_BLOCK * TPW;  // 64
    int blocks = (n_tok + tokens_per_block - 1) / tokens_per_block;

    cbow_subword_kernel<<<blocks, THREADS_PER_BLOCK>>>(seq, pre, post, W, out, n_tok);
}

// round 6
// speedup vs baseline: 1.0625x; 1.0625x over previous
#include <cuda_runtime.h>

// out[t, :] = W[seq[t], :] + W[pre[t], :] + W[post[t], :]
// D = 128 floats (512B row). One warp per 4 tokens; lane l -> float4 #l.
// L2(LTS)-throughput bound (~270MB/launch through L2, at ~11.4 TB/s cap).
// TPW=4 is the occ*MLP sweet spot (R3 showed TPW=8 collapses occupancy).
// __ldcg: random gathers have ~0% L1 hit rate, skip L1 allocation.
// __stcs: keep the 51MB weight table L2-resident across graph replays.

#define EMBED_VEC 32
#define THREADS_PER_BLOCK 256
#define WARPS_PER_BLOCK (THREADS_PER_BLOCK / 32)
#define TPW 4   // tokens per warp

__global__ __launch_bounds__(THREADS_PER_BLOCK)
void cbow_subword_kernel(const int* __restrict__ seq,
                         const int* __restrict__ pre,
                         const int* __restrict__ post,
                         const float4* __restrict__ W,
                         float4* __restrict__ out,
                         int n_tok) {
    int warp = blockIdx.x * WARPS_PER_BLOCK + (threadIdx.x >> 5);
    int lane = threadIdx.x & 31;
    long long t0 = (long long)warp * TPW;
    if (t0 >= n_tok) return;

    if (t0 + TPW <= n_tok) {
        // Vectorized index loads (t0 is 4-aligned): 3 broadcasts.
        int4 s = __ldg((const int4*)(seq  + t0));
        int4 p = __ldg((const int4*)(pre  + t0));
        int4 q = __ldg((const int4*)(post + t0));
        int ia[TPW] = {s.x, s.y, s.z, s.w};
        int ib[TPW] = {p.x, p.y, p.z, p.w};
        int ic[TPW] = {q.x, q.y, q.z, q.w};

        // 12 independent gathers issued before first use (MLP=12).
        float4 va[TPW], vb[TPW], vc[TPW];
        #pragma unroll
        for (int j = 0; j < TPW; j++) va[j] = __ldcg(W + (size_t)ia[j] * EMBED_VEC + lane);
        #pragma unroll
        for (int j = 0; j < TPW; j++) vb[j] = __ldcg(W + (size_t)ib[j] * EMBED_VEC + lane);
        #pragma unroll
        for (int j = 0; j < TPW; j++) vc[j] = __ldcg(W + (size_t)ic[j] * EMBED_VEC + lane);

        #pragma unroll
        for (int j = 0; j < TPW; j++) {
            float4 r;
            r.x = va[j].x + vb[j].x + vc[j].x;
            r.y = va[j].y + vb[j].y + vc[j].y;
            r.z = va[j].z + vb[j].z + vc[j].z;
            r.w = va[j].w + vb[j].w + vc[j].w;
            __stcs(out + (size_t)(t0 + j) * EMBED_VEC + lane, r);
        }
    } else {
        // Tail (not hit for 131072 tokens).
        for (long long t = t0; t < n_tok; t++) {
            int i0 = __ldg(seq + t), i1 = __ldg(pre + t), i2 = __ldg(post + t);
            float4 a = __ldcg(W + (size_t)i0 * EMBED_VEC + lane);
            float4 b = __ldcg(W + (size_t)i1 * EMBED_VEC + lane);
            float4 c = __ldcg(W + (size_t)i2 * EMBED_VEC + lane);
            float4 r;
            r.x = a.x + b.x + c.x;
            r.y = a.y + b.y + c.y;
            r.z = a.z + b.z + c.z;
            r.w = a.w + b.w + c.w;
            __stcs(out + (size_t)t * EMBED_VEC + lane, r);
        }
    }
}

extern "C" void kernel_launch(void* const* d_in, const int* in_sizes, int n_in,
                              void* d_out, int out_size) {
    const int*    seq  = (const int*)d_in[0];
    const int*    pre  = (const int*)d_in[1];
    const int*    post = (const int*)d_in[2];
    const float4* W    = (const float4*)d_in[3];
    float4*       out  = (float4*)d_out;

    int n_tok = in_sizes[0];  // 131072
    int tokens_per_block = WARPS_PER_BLOCK * TPW;  // 32
    int blocks = (n_tok + tokens_per_block - 1) / tokens_per_block;

    cbow_subword_kernel<<<blocks, THREADS_PER_BLOCK>>>(seq, pre, post, W, out, n_tok);
}

// round 9
// speedup vs baseline: 1.1586x; 1.0904x over previous
#include <cuda_runtime.h>

// out[t, :] = W[seq[t], :] + W[pre[t], :] + W[post[t], :]
// D = 128 floats (512B row); lane l -> float4 #l; warp covers a full row.
// LTS(L2-crossbar)-throughput bound: ~270MB SM<->L2 per launch at the
// ~11.4 TB/s chip cap; bytes irreducible (uniform-random gathers, 98K
// distinct rows). Persistent SINGLE-WAVE grid: 256-thr blocks occupy at
// most 4 CTAs/SM (32-warp cap), so one wave = 148*4 = 592 blocks. Each
// warp grid-strides over 4-token chunks with R2's proven inner body.

#define EMBED_VEC 32
#define THREADS_PER_BLOCK 256
#define WARPS_PER_BLOCK (THREADS_PER_BLOCK / 32)
#define TPW 4                 // tokens per warp-chunk
#define GRID_BLOCKS 592       // 148 SMs * 4 resident CTAs (32-warp cap)

__global__ __launch_bounds__(THREADS_PER_BLOCK)
void cbow_subword_kernel(const int* __restrict__ seq,
                         const int* __restrict__ pre,
                         const int* __restrict__ post,
                         const float4* __restrict__ W,
                         float4* __restrict__ out,
                         int n_tok) {
    const int warp = blockIdx.x * WARPS_PER_BLOCK + (threadIdx.x >> 5);
    const int lane = threadIdx.x & 31;
    const int n_warps = gridDim.x * WARPS_PER_BLOCK;
    const long long chunk_stride = (long long)n_warps * TPW;

    for (long long t0 = (long long)warp * TPW; t0 < n_tok; t0 += chunk_stride) {
        if (t0 + TPW <= n_tok) {
            // 3 vectorized index broadcasts (t0 is 4-aligned).
            int4 s = __ldg((const int4*)(seq  + t0));
            int4 p = __ldg((const int4*)(pre  + t0));
            int4 q = __ldg((const int4*)(post + t0));
            int ia[TPW] = {s.x, s.y, s.z, s.w};
            int ib[TPW] = {p.x, p.y, p.z, p.w};
            int ic[TPW] = {q.x, q.y, q.z, q.w};

            // 12 independent gathers issued before first use (MLP=12).
            float4 va[TPW], vb[TPW], vc[TPW];
            #pragma unroll
            for (int j = 0; j < TPW; j++) va[j] = __ldg(W + (size_t)ia[j] * EMBED_VEC + lane);
            #pragma unroll
            for (int j = 0; j < TPW; j++) vb[j] = __ldg(W + (size_t)ib[j] * EMBED_VEC + lane);
            #pragma unroll
            for (int j = 0; j < TPW; j++) vc[j] = __ldg(W + (size_t)ic[j] * EMBED_VEC + lane);

            #pragma unroll
            for (int j = 0; j < TPW; j++) {
                float4 r;
                r.x = va[j].x + vb[j].x + vc[j].x;
                r.y = va[j].y + vb[j].y + vc[j].y;
                r.z = va[j].z + vb[j].z + vc[j].z;
                r.w = va[j].w + vb[j].w + vc[j].w;
                // Streaming store: keep the 51MB weight table L2-resident.
                __stcs(out + (size_t)(t0 + j) * EMBED_VEC + lane, r);
            }
        } else {
            for (long long t = t0; t < n_tok; t++) {
                int i0 = __ldg(seq + t), i1 = __ldg(pre + t), i2 = __ldg(post + t);
                float4 a = __ldg(W + (size_t)i0 * EMBED_VEC + lane);
                float4 b = __ldg(W + (size_t)i1 * EMBED_VEC + lane);
                float4 c = __ldg(W + (size_t)i2 * EMBED_VEC + lane);
                float4 r;
                r.x = a.x + b.x + c.x;
                r.y = a.y + b.y + c.y;
                r.z = a.z + b.z + c.z;
                r.w = a.w + b.w + c.w;
                __stcs(out + (size_t)t * EMBED_VEC + lane, r);
            }
        }
    }
}

extern "C" void kernel_launch(void* const* d_in, const int* in_sizes, int n_in,
                              void* d_out, int out_size) {
    const int*    seq  = (const int*)d_in[0];
    const int*    pre  = (const int*)d_in[1];
    const int*    post = (const int*)d_in[2];
    const float4* W    = (const float4*)d_in[3];
    float4*       out  = (float4*)d_out;

    int n_tok = in_sizes[0];  // 131072

    // Single-wave persistent grid; shrink for tiny inputs.
    int chunks = (n_tok + TPW - 1) / TPW;
    int blocks_needed = (chunks + WARPS_PER_BLOCK - 1) / WARPS_PER_BLOCK;
    int blocks = GRID_BLOCKS < blocks_needed ? GRID_BLOCKS : blocks_needed;
    if (blocks < 1) blocks = 1;

    cbow_subword_kernel<<<blocks, THREADS_PER_BLOCK>>>(seq, pre, post, W, out, n_tok);
}